// round 14
// baseline (speedup 1.0000x reference)
#include <cuda_runtime.h>
#include <cuda_bf16.h>
#include <math.h>
#include <stdint.h>

#define NN 8192
#define NROWS 9
#define RAD3 768
#define NTH 256

__device__ float g_node[(size_t)NN * NROWS * 128];
// pre-packed B-fragments (bf16x2 words), [plane 0=hi,1=lo]
__device__ __align__(16) uint32_t g_w2p[2][6 * 8 * 4 * 32 * 4];     // [b][jt][kt][lane][j]
__device__ __align__(16) uint32_t g_fcp[2][6 * 16 * 8 * 32 * 4];    // [b][nt][kt][lane][j]

__device__ __forceinline__ void split_bf16(float v, __nv_bfloat16& hi, __nv_bfloat16& lo) {
    hi = __float2bfloat16(v);
    lo = __float2bfloat16(v - __bfloat162float(hi));
}

// ============ K01: node projection + fragment pre-pack ============
__global__ void k01(const float* __restrict__ node_in, const float* __restrict__ dot_w,
                    const float* __restrict__ dot_b, const float* __restrict__ w2,
                    const float* __restrict__ fcw) {
    int gt = blockIdx.x * 256 + threadIdx.x;
    if (gt < 24576) {                                  // w2 frag pack
        int j = gt & 3, l = (gt >> 2) & 31, kt = (gt >> 7) & 3;
        int jt = (gt >> 9) & 7, b = gt >> 12;
        int jg = b * 128 + jt * 16 + ((j >> 1) << 3) + (l >> 2);
        int k  = kt * 16 + ((j & 1) << 3) + ((l & 3) << 1);
        float v0 = w2[(size_t)jg * 64 + k], v1 = w2[(size_t)jg * 64 + k + 1];
        __nv_bfloat16 h0, l0, h1, l1;
        split_bf16(v0, h0, l0); split_bf16(v1, h1, l1);
        __nv_bfloat162 ph(h0, h1), pl(l0, l1);
        g_w2p[0][gt] = *(uint32_t*)&ph;
        g_w2p[1][gt] = *(uint32_t*)&pl;
    } else if (gt < 24576 + 98304) {                   // fc frag pack
        int i = gt - 24576;
        int j = i & 3, l = (i >> 2) & 31, kt = (i >> 7) & 7;
        int nt = (i >> 10) & 15, b = i >> 14;
        int n = nt * 16 + ((j >> 1) << 3) + (l >> 2);
        int k = b * 128 + kt * 16 + ((j & 1) << 3) + ((l & 3) << 1);
        float v0 = fcw[(size_t)n * RAD3 + k], v1 = fcw[(size_t)n * RAD3 + k + 1];
        __nv_bfloat16 h0, l0, h1, l1;
        split_bf16(v0, h0, l0); split_bf16(v1, h1, l1);
        __nv_bfloat162 ph(h0, h1), pl(l0, l1);
        g_fcp[0][i] = *(uint32_t*)&ph;
        g_fcp[1][i] = *(uint32_t*)&pl;
    }
    __shared__ __align__(16) float sm[NROWS * 128];
    int n = blockIdx.x;
    const float* src = node_in + (size_t)n * NROWS * 128;
    for (int i = threadIdx.x; i < NROWS * 128; i += blockDim.x) sm[i] = src[i];
    __syncthreads();
    for (int idx = threadIdx.x; idx < NROWS * 128; idx += blockDim.x) {
        int m = idx >> 7, d = idx & 127;
        int l = (m == 0) ? 0 : (m < 4 ? 1 : 2);
        const float4* w = (const float4*)(dot_w + (size_t)l * 16384 + (size_t)d * 128);
        const float4* x = (const float4*)(sm + m * 128);
        float acc = (m == 0) ? dot_b[d] : 0.f;
#pragma unroll
        for (int c4 = 0; c4 < 32; c4++) {
            float4 wv = __ldg(&w[c4]); float4 xv = x[c4];
            acc += wv.x * xv.x + wv.y * xv.y + wv.z * xv.z + wv.w * xv.w;
        }
        g_node[(size_t)n * NROWS * 128 + idx] = acc;
    }
}

// ============ helpers ============
__device__ __forceinline__ uint32_t sptr(const void* p) {
    return (uint32_t)__cvta_generic_to_shared(p);
}
__device__ __forceinline__ void ldmx4(uint32_t a, uint32_t& r0, uint32_t& r1,
                                      uint32_t& r2, uint32_t& r3) {
    asm volatile("ldmatrix.sync.aligned.m8n8.x4.shared.b16 {%0,%1,%2,%3}, [%4];"
                 : "=r"(r0), "=r"(r1), "=r"(r2), "=r"(r3) : "r"(a));
}
__device__ __forceinline__ void mma16816(float* c, const uint32_t* a, const uint32_t* b) {
    asm volatile("mma.sync.aligned.m16n8k16.row.col.f32.bf16.bf16.f32 "
                 "{%0,%1,%2,%3}, {%4,%5,%6,%7}, {%8,%9}, {%0,%1,%2,%3};"
                 : "+f"(c[0]), "+f"(c[1]), "+f"(c[2]), "+f"(c[3])
                 : "r"(a[0]), "r"(a[1]), "r"(a[2]), "r"(a[3]), "r"(b[0]), "r"(b[1]));
}

// ============ smem layout (bytes) ============
#define OFF_X0  0          // 16896: xs / x0 (32x132 f)
#define OFF_Y   16896      // 17408: Yh (32x136 bf16) + Yl
#define OFF_H   34304      // 9216: h0s (32x68 f) | Hh/Hl (32x72 bf16)
#define OFF_H1  43520      // 8704: h1s (32x68 f)
#define OFF_NF  52224      // 4608
#define OFF_SH  56832      // 1536
#define OFF_IDX 58368      // 128
#define SMEM_B  58496

// ============ K2: 32 edges/block, LDG weights everywhere ============
__global__ void __launch_bounds__(NTH, 2) k2(
    const float* __restrict__ x_edge, const float* __restrict__ edge_vec,
    const int* __restrict__ sp_idx,
    const float* __restrict__ w0, const float* __restrict__ b0,
    const float* __restrict__ w1, const float* __restrict__ b1,
    const float* __restrict__ b2,
    const float* __restrict__ g0, const float* __restrict__ bb0,
    const float* __restrict__ g1, const float* __restrict__ bb1,
    const float* __restrict__ fc_b,
    const float* __restrict__ ln_g, const float* __restrict__ ln_b,
    const float* __restrict__ alpha_dot, float* __restrict__ out)
{
    extern __shared__ __align__(16) char smem[];
    float* x0s = (float*)(smem + OFF_X0);
    float* h0s = (float*)(smem + OFF_H);
    float* h1s = (float*)(smem + OFF_H1);
    float* nfs = (float*)(smem + OFF_NF);
    float* shs = (float*)(smem + OFF_SH);
    int* idxs  = (int*)(smem + OFF_IDX);
    __nv_bfloat16* Yh = (__nv_bfloat16*)(smem + OFF_Y);            // 32x136
    __nv_bfloat16* Yl = (__nv_bfloat16*)(smem + OFF_Y + 8704);
    __nv_bfloat16* Hh = (__nv_bfloat16*)(smem + OFF_H);            // 32x72
    __nv_bfloat16* Hl = (__nv_bfloat16*)(smem + OFF_H + 4608);

    int tid = threadIdx.x;
    int n = blockIdx.x, eg0 = n * 32;

    // ---- stage ----
    if (tid < 32) idxs[tid] = sp_idx[eg0 + tid];
    for (int i = tid; i < NROWS * 128; i += NTH)
        nfs[i] = g_node[(size_t)n * NROWS * 128 + i];
    for (int i = tid; i < 32 * 128; i += NTH) {
        int e = i >> 7, c = i & 127;
        x0s[e * 132 + c] = x_edge[(size_t)(eg0 + e) * 128 + c];
    }
    if (tid < 32) {
        const float* ev = edge_vec + (size_t)(eg0 + tid) * 3;
        float x = ev[0], y = ev[1], z = ev[2];
        float inv = 1.f / fmaxf(sqrtf(x * x + y * y + z * z), 1e-12f);
        x *= inv; y *= inv; z *= inv;
        float* s = shs + tid * 12;
        const float C0 = 0.28209479177387814f, C1 = 0.4886025119029199f;
        const float C2 = 0.6307831305050401f, S3 = 1.7320508075688772f;
        s[0] = C0; s[1] = C1 * x; s[2] = C1 * y; s[3] = C1 * z;
        s[4] = C2 * S3 * x * z; s[5] = C2 * S3 * x * y;
        s[6] = C2 * (y * y - 0.5f * (x * x + z * z)); s[7] = C2 * S3 * y * z;
        s[8] = C2 * 0.5f * S3 * (z * z - x * x);
    }
    __syncthreads();

    int tx = tid & 15, ty = tid >> 4;
    int o4 = tx * 4, e2 = ty * 2;

    // ---- rad0: 32e x 64o, k=128, weights via LDG ----
    {
        float a[2][4];
        float4 bv = *(const float4*)&b0[o4];
#pragma unroll
        for (int i = 0; i < 2; i++) { a[i][0]=bv.x; a[i][1]=bv.y; a[i][2]=bv.z; a[i][3]=bv.w; }
#pragma unroll 4
        for (int k4 = 0; k4 < 32; k4++) {
            float4 xv[2], wv[4];
#pragma unroll
            for (int i = 0; i < 2; i++) xv[i] = *(const float4*)&x0s[(e2 + i) * 132 + k4 * 4];
#pragma unroll
            for (int j = 0; j < 4; j++) wv[j] = __ldg((const float4*)&w0[(o4 + j) * 128 + k4 * 4]);
#pragma unroll
            for (int i = 0; i < 2; i++)
#pragma unroll
                for (int j = 0; j < 4; j++)
                    a[i][j] += xv[i].x*wv[j].x + xv[i].y*wv[j].y + xv[i].z*wv[j].z + xv[i].w*wv[j].w;
        }
#pragma unroll
        for (int i = 0; i < 2; i++)
            *(float4*)&h0s[(e2 + i) * 68 + o4] = make_float4(a[i][0], a[i][1], a[i][2], a[i][3]);
    }
    __syncthreads();
    {   // LN+SiLU h0 (8 threads/edge)
        int e = tid >> 3, p = tid & 7;
        float* row = h0s + e * 68 + p * 8;
        float v[8], s1 = 0.f, s2 = 0.f;
#pragma unroll
        for (int i = 0; i < 8; i++) { v[i] = row[i]; s1 += v[i]; s2 += v[i]*v[i]; }
        s1 += __shfl_xor_sync(~0u, s1, 1); s2 += __shfl_xor_sync(~0u, s2, 1);
        s1 += __shfl_xor_sync(~0u, s1, 2); s2 += __shfl_xor_sync(~0u, s2, 2);
        s1 += __shfl_xor_sync(~0u, s1, 4); s2 += __shfl_xor_sync(~0u, s2, 4);
        float mean = s1 * (1.f/64.f), var = s2 * (1.f/64.f) - mean*mean;
        float rs = rsqrtf(var + 1e-5f);
#pragma unroll
        for (int i = 0; i < 8; i++) {
            float z = (v[i] - mean) * rs * __ldg(&g0[p*8+i]) + __ldg(&bb0[p*8+i]);
            row[i] = z / (1.f + expf(-z));
        }
    }
    __syncthreads();
    // ---- rad1: 32e x 64o, k=64, weights via LDG ----
    {
        float a[2][4];
        float4 bv = *(const float4*)&b1[o4];
#pragma unroll
        for (int i = 0; i < 2; i++) { a[i][0]=bv.x; a[i][1]=bv.y; a[i][2]=bv.z; a[i][3]=bv.w; }
#pragma unroll 4
        for (int k4 = 0; k4 < 16; k4++) {
            float4 xv[2], wv[4];
#pragma unroll
            for (int i = 0; i < 2; i++) xv[i] = *(const float4*)&h0s[(e2 + i) * 68 + k4 * 4];
#pragma unroll
            for (int j = 0; j < 4; j++) wv[j] = __ldg((const float4*)&w1[(o4 + j) * 64 + k4 * 4]);
#pragma unroll
            for (int i = 0; i < 2; i++)
#pragma unroll
                for (int j = 0; j < 4; j++)
                    a[i][j] += xv[i].x*wv[j].x + xv[i].y*wv[j].y + xv[i].z*wv[j].z + xv[i].w*wv[j].w;
        }
#pragma unroll
        for (int i = 0; i < 2; i++)
            *(float4*)&h1s[(e2 + i) * 68 + o4] = make_float4(a[i][0], a[i][1], a[i][2], a[i][3]);
    }
    __syncthreads();   // rad1's h0s reads done; h0s region free for H
    {   // LN+SiLU h1 -> split -> Hh/Hl
        int e = tid >> 3, p = tid & 7;
        const float* row = h1s + e * 68 + p * 8;
        float v[8], s1 = 0.f, s2 = 0.f;
#pragma unroll
        for (int i = 0; i < 8; i++) { v[i] = row[i]; s1 += v[i]; s2 += v[i]*v[i]; }
        s1 += __shfl_xor_sync(~0u, s1, 1); s2 += __shfl_xor_sync(~0u, s2, 1);
        s1 += __shfl_xor_sync(~0u, s1, 2); s2 += __shfl_xor_sync(~0u, s2, 2);
        s1 += __shfl_xor_sync(~0u, s1, 4); s2 += __shfl_xor_sync(~0u, s2, 4);
        float mean = s1 * (1.f/64.f), var = s2 * (1.f/64.f) - mean*mean;
        float rs = rsqrtf(var + 1e-5f);
#pragma unroll
        for (int i = 0; i < 8; i++) {
            float z = (v[i] - mean) * rs * __ldg(&g1[p*8+i]) + __ldg(&bb1[p*8+i]);
            float sil = z / (1.f + expf(-z));
            __nv_bfloat16 hi, lo;
            split_bf16(sil, hi, lo);
            Hh[e * 72 + p * 8 + i] = hi;
            Hl[e * 72 + p * 8 + i] = lo;
        }
    }
    __syncthreads();

    // ---- warp roles ----
    int lane = tid & 31, w = tid >> 5;
    int we = w & 1,  jg = w >> 1;        // w2: e we*16, j jg*32
    int weF = w & 1, wnF = w >> 1;       // FC: e weF*16, n wnF*64
    int g = lane >> 3, r = lane & 7;
    int h_row = r + ((g & 1) << 3), h_col = (g >> 1) << 3;
    int e_lo = lane >> 2, q = lane & 3;

    float acc[4][2][4];                  // FC accum: [nt'][n8][frag]
#pragma unroll
    for (int a1 = 0; a1 < 4; a1++)
#pragma unroll
        for (int a2 = 0; a2 < 2; a2++)
#pragma unroll
            for (int a3 = 0; a3 < 4; a3++) acc[a1][a2][a3] = 0.f;

    for (int b = 0; b < 6; b++) {
        // ---- x0 gather ----
        for (int i = tid; i < 32 * 128; i += NTH) {
            int e = i >> 7, d = i & 127;
            const float* s = shs + e * 12;
            const float* src = (b & 1) ? g_node + (size_t)idxs[e] * (NROWS * 128) : nfs;
            float x0;
            if      (b < 2) x0 = s[0] * src[d];
            else if (b < 4) x0 = s[1]*src[128+d] + s[2]*src[256+d] + s[3]*src[384+d];
            else            x0 = s[4]*src[512+d] + s[5]*src[640+d] + s[6]*src[768+d]
                               + s[7]*src[896+d] + s[8]*src[1024+d];
            x0s[e * 132 + d] = x0;
        }
        __syncthreads();                               // S1: x0 visible

        // ---- w2-mma: 16e x 32j over 64k, B-frags via LDG ----
        float acc2[2][2][4];
#pragma unroll
        for (int jt = 0; jt < 2; jt++)
#pragma unroll
            for (int n8 = 0; n8 < 2; n8++)
#pragma unroll
                for (int c = 0; c < 4; c++) acc2[jt][n8][c] = 0.f;
#pragma unroll
        for (int kk = 0; kk < 4; kk++) {
            uint32_t ah[4], al[4];
            ldmx4(sptr(&Hh[(we * 16 + h_row) * 72 + kk * 16 + h_col]), ah[0], ah[1], ah[2], ah[3]);
            ldmx4(sptr(&Hl[(we * 16 + h_row) * 72 + kk * 16 + h_col]), al[0], al[1], al[2], al[3]);
#pragma unroll
            for (int jt = 0; jt < 2; jt++) {
                size_t ti = ((((size_t)b * 8 + jg * 2 + jt) * 4 + kk) * 32 + lane) * 4;
                uint4 bh = __ldg((const uint4*)&g_w2p[0][ti]);
                uint4 bl = __ldg((const uint4*)&g_w2p[1][ti]);
#pragma unroll
                for (int n8 = 0; n8 < 2; n8++) {
                    const uint32_t* bhp = n8 ? &bh.z : &bh.x;
                    const uint32_t* blp = n8 ? &bl.z : &bl.x;
                    float* c = acc2[jt][n8];
                    mma16816(c, ah, bhp);
                    mma16816(c, al, bhp);
                    mma16816(c, ah, blp);
                }
            }
        }

        // ---- y = x0*(m0+b2) -> Yh/Yl (separate region; x0 read inline) ----
#pragma unroll
        for (int jt = 0; jt < 2; jt++) {
#pragma unroll
            for (int n8 = 0; n8 < 2; n8++) {
                int jl = jg * 32 + jt * 16 + n8 * 8 + 2 * q;
                int jgl = b * 128 + jl;
                float b20 = __ldg(&b2[jgl]), b21 = __ldg(&b2[jgl + 1]);
#pragma unroll
                for (int ri = 0; ri < 2; ri++) {
                    int e = we * 16 + e_lo + ri * 8;
                    float2 xv = *(const float2*)&x0s[e * 132 + jl];
                    float y0 = xv.x * (acc2[jt][n8][ri * 2]     + b20);
                    float y1 = xv.y * (acc2[jt][n8][ri * 2 + 1] + b21);
                    __nv_bfloat16 h0b, l0b, h1b, l1b;
                    split_bf16(y0, h0b, l0b); split_bf16(y1, h1b, l1b);
                    *(__nv_bfloat162*)&Yh[e * 136 + jl] = __nv_bfloat162(h0b, h1b);
                    *(__nv_bfloat162*)&Yl[e * 136 + jl] = __nv_bfloat162(l0b, l1b);
                }
            }
        }
        __syncthreads();                               // S2: Y visible

        // ---- FC: 16e x 64n over 128k, B-frags via LDG ----
#pragma unroll
        for (int kt = 0; kt < 8; kt++) {
            uint32_t ah[4], al[4];
            ldmx4(sptr(&Yh[(weF * 16 + h_row) * 136 + kt * 16 + h_col]), ah[0], ah[1], ah[2], ah[3]);
            ldmx4(sptr(&Yl[(weF * 16 + h_row) * 136 + kt * 16 + h_col]), al[0], al[1], al[2], al[3]);
#pragma unroll
            for (int nt = 0; nt < 4; nt++) {
                size_t ti = ((((size_t)b * 16 + wnF * 4 + nt) * 8 + kt) * 32 + lane) * 4;
                uint4 bh = __ldg((const uint4*)&g_fcp[0][ti]);
                uint4 bl = __ldg((const uint4*)&g_fcp[1][ti]);
#pragma unroll
                for (int n8 = 0; n8 < 2; n8++) {
                    const uint32_t* bhp = n8 ? &bh.z : &bh.x;
                    const uint32_t* blp = n8 ? &bl.z : &bl.x;
                    float* c = acc[nt][n8];
                    mma16816(c, ah, bhp);
                    mma16816(c, al, bhp);
                    mma16816(c, ah, blp);
                }
            }
        }
        __syncthreads();                               // S3: Y+x0 consumed
    }

    // ---- epilogue: warp (weF, wnF): rows weF*16.., heads wnF*2 + ht ----
#pragma unroll
    for (int ht = 0; ht < 2; ht++) {
        int head = wnF * 2 + ht;
#pragma unroll
        for (int ri = 0; ri < 2; ri++) {
            int erow = eg0 + weF * 16 + e_lo + ri * 8;
            float v[8], s1 = 0.f, s2 = 0.f;
#pragma unroll
            for (int ntl = 0; ntl < 2; ntl++)
#pragma unroll
                for (int n8 = 0; n8 < 2; n8++)
#pragma unroll
                    for (int c = 0; c < 2; c++) {
                        int d = ntl * 16 + n8 * 8 + 2 * q + c;
                        float val = acc[ht * 2 + ntl][n8][ri * 2 + c] + __ldg(&fc_b[head * 32 + d]);
                        v[ntl * 4 + n8 * 2 + c] = val;
                        s1 += val; s2 += val * val;
                    }
            s1 += __shfl_xor_sync(~0u, s1, 1); s2 += __shfl_xor_sync(~0u, s2, 1);
            s1 += __shfl_xor_sync(~0u, s1, 2); s2 += __shfl_xor_sync(~0u, s2, 2);
            float mean = s1 * (1.f / 32.f), var = s2 * (1.f / 32.f) - mean * mean;
            float rs = rsqrtf(var + 1e-5f);
            float p = 0.f;
#pragma unroll
            for (int j = 0; j < 8; j++) {
                int ntl = j >> 2, n8 = (j >> 1) & 1, c = j & 1;
                int d = ntl * 16 + n8 * 8 + 2 * q + c;
                float z = (v[j] - mean) * rs * __ldg(&ln_g[d]) + __ldg(&ln_b[d]);
                float sg = 1.f / (1.f + expf(-z));
                float slr = 0.6f * z + 0.4f * z * (2.f * sg - 1.f);
                p += slr * __ldg(&alpha_dot[head * 32 + d]);
            }
            p += __shfl_xor_sync(~0u, p, 1);
            p += __shfl_xor_sync(~0u, p, 2);
            if (q == 0)
                out[(size_t)erow * 8 + head] = p;
        }
    }
}

// ============ launch ============
extern "C" void kernel_launch(void* const* d_in, const int* in_sizes, int n_in,
                              void* d_out, int out_size) {
    const float* x_edge   = (const float*)d_in[0];
    const float* node_in  = (const float*)d_in[1];
    const float* edge_vec = (const float*)d_in[2];
    const int*   sp       = (const int*)d_in[3];
    const float* dot_w    = (const float*)d_in[4];
    const float* dot_b    = (const float*)d_in[5];
    const float* w0  = (const float*)d_in[6];
    const float* b0  = (const float*)d_in[7];
    const float* w1  = (const float*)d_in[8];
    const float* b1  = (const float*)d_in[9];
    const float* w2  = (const float*)d_in[10];
    const float* b2  = (const float*)d_in[11];
    const float* g0  = (const float*)d_in[12];
    const float* bb0 = (const float*)d_in[13];
    const float* g1  = (const float*)d_in[14];
    const float* bb1 = (const float*)d_in[15];
    const float* fcw = (const float*)d_in[16];
    const float* fcb = (const float*)d_in[17];
    const float* lng = (const float*)d_in[18];
    const float* lnb = (const float*)d_in[19];
    const float* ad  = (const float*)d_in[20];
    float* out = (float*)d_out;

    k01<<<NN, 256>>>(node_in, dot_w, dot_b, w2, fcw);

    cudaFuncSetAttribute(k2, cudaFuncAttributeMaxDynamicSharedMemorySize, SMEM_B);
    k2<<<NN, NTH, SMEM_B>>>(x_edge, edge_vec, sp,
                            w0, b0, w1, b1, b2, g0, bb0, g1, bb1,
                            fcb, lng, lnb, ad, out);
}

// round 15
// speedup vs baseline: 1.4262x; 1.4262x over previous
#include <cuda_runtime.h>
#include <cuda_bf16.h>
#include <math.h>
#include <stdint.h>

#define NN 8192
#define NROWS 9
#define RAD3 768
#define NTH 256

__device__ float g_node[(size_t)NN * NROWS * 128];
// pre-packed B-fragments (bf16x2 words), [plane 0=hi,1=lo]
__device__ __align__(16) uint32_t g_w2p[2][6 * 8 * 4 * 32 * 4];     // [b][jt][kt][lane][j]
__device__ __align__(16) uint32_t g_fcp[2][6 * 16 * 8 * 32 * 4];    // [b][nt][kt][lane][j]

__device__ __forceinline__ void split_bf16(float v, __nv_bfloat16& hi, __nv_bfloat16& lo) {
    hi = __float2bfloat16(v);
    lo = __float2bfloat16(v - __bfloat162float(hi));
}

// ============ K01: node projection + fragment pre-pack ============
__global__ void k01(const float* __restrict__ node_in, const float* __restrict__ dot_w,
                    const float* __restrict__ dot_b, const float* __restrict__ w2,
                    const float* __restrict__ fcw) {
    int gt = blockIdx.x * 256 + threadIdx.x;
    if (gt < 24576) {                                  // w2 frag pack
        int j = gt & 3, l = (gt >> 2) & 31, kt = (gt >> 7) & 3;
        int jt = (gt >> 9) & 7, b = gt >> 12;
        int jg = b * 128 + jt * 16 + ((j >> 1) << 3) + (l >> 2);
        int k  = kt * 16 + ((j & 1) << 3) + ((l & 3) << 1);
        float v0 = w2[(size_t)jg * 64 + k], v1 = w2[(size_t)jg * 64 + k + 1];
        __nv_bfloat16 h0, l0, h1, l1;
        split_bf16(v0, h0, l0); split_bf16(v1, h1, l1);
        __nv_bfloat162 ph(h0, h1), pl(l0, l1);
        g_w2p[0][gt] = *(uint32_t*)&ph;
        g_w2p[1][gt] = *(uint32_t*)&pl;
    } else if (gt < 24576 + 98304) {                   // fc frag pack
        int i = gt - 24576;
        int j = i & 3, l = (i >> 2) & 31, kt = (i >> 7) & 7;
        int nt = (i >> 10) & 15, b = i >> 14;
        int n = nt * 16 + ((j >> 1) << 3) + (l >> 2);
        int k = b * 128 + kt * 16 + ((j & 1) << 3) + ((l & 3) << 1);
        float v0 = fcw[(size_t)n * RAD3 + k], v1 = fcw[(size_t)n * RAD3 + k + 1];
        __nv_bfloat16 h0, l0, h1, l1;
        split_bf16(v0, h0, l0); split_bf16(v1, h1, l1);
        __nv_bfloat162 ph(h0, h1), pl(l0, l1);
        g_fcp[0][i] = *(uint32_t*)&ph;
        g_fcp[1][i] = *(uint32_t*)&pl;
    }
    __shared__ __align__(16) float sm[NROWS * 128];
    int n = blockIdx.x;
    const float* src = node_in + (size_t)n * NROWS * 128;
    for (int i = threadIdx.x; i < NROWS * 128; i += blockDim.x) sm[i] = src[i];
    __syncthreads();
    for (int idx = threadIdx.x; idx < NROWS * 128; idx += blockDim.x) {
        int m = idx >> 7, d = idx & 127;
        int l = (m == 0) ? 0 : (m < 4 ? 1 : 2);
        const float4* w = (const float4*)(dot_w + (size_t)l * 16384 + (size_t)d * 128);
        const float4* x = (const float4*)(sm + m * 128);
        float acc = (m == 0) ? dot_b[d] : 0.f;
#pragma unroll
        for (int c4 = 0; c4 < 32; c4++) {
            float4 wv = __ldg(&w[c4]); float4 xv = x[c4];
            acc += wv.x * xv.x + wv.y * xv.y + wv.z * xv.z + wv.w * xv.w;
        }
        g_node[(size_t)n * NROWS * 128 + idx] = acc;
    }
}

// ============ helpers ============
__device__ __forceinline__ uint32_t sptr(const void* p) {
    return (uint32_t)__cvta_generic_to_shared(p);
}
__device__ __forceinline__ void ldmx4(uint32_t a, uint32_t& r0, uint32_t& r1,
                                      uint32_t& r2, uint32_t& r3) {
    asm volatile("ldmatrix.sync.aligned.m8n8.x4.shared.b16 {%0,%1,%2,%3}, [%4];"
                 : "=r"(r0), "=r"(r1), "=r"(r2), "=r"(r3) : "r"(a));
}
__device__ __forceinline__ void mma16816(float* c, const uint32_t* a, const uint32_t* b) {
    asm volatile("mma.sync.aligned.m16n8k16.row.col.f32.bf16.bf16.f32 "
                 "{%0,%1,%2,%3}, {%4,%5,%6,%7}, {%8,%9}, {%0,%1,%2,%3};"
                 : "+f"(c[0]), "+f"(c[1]), "+f"(c[2]), "+f"(c[3])
                 : "r"(a[0]), "r"(a[1]), "r"(a[2]), "r"(a[3]), "r"(b[0]), "r"(b[1]));
}

// ============ smem layout (bytes) ============
#define OFF_X0  0          // 16896: xs / x0 chunk (32x132 f)
#define OFF_W0  16896      // 33792: w0s (64x132 f) | Yh (32x136 bf16)+Yl after prologue
#define OFF_W1  50688      // 17408: w1s (64x68 f)
#define OFF_H0  68096      // 9216: h0s (32x68 f) | Hh/Hl (32x72 bf16)
#define OFF_H1  77312      // 8704: h1s (32x68 f)
#define OFF_NF  86016      // 4608
#define OFF_SH  90624      // 1536
#define OFF_IDX 92160      // 128
#define SMEM_B  92288

// ============ K2: 32 edges/block ============
__global__ void __launch_bounds__(NTH, 2) k2(
    const float* __restrict__ x_edge, const float* __restrict__ edge_vec,
    const int* __restrict__ sp_idx,
    const float* __restrict__ w0, const float* __restrict__ b0,
    const float* __restrict__ w1, const float* __restrict__ b1,
    const float* __restrict__ b2,
    const float* __restrict__ g0, const float* __restrict__ bb0,
    const float* __restrict__ g1, const float* __restrict__ bb1,
    const float* __restrict__ fc_b,
    const float* __restrict__ ln_g, const float* __restrict__ ln_b,
    const float* __restrict__ alpha_dot, float* __restrict__ out)
{
    extern __shared__ __align__(16) char smem[];
    float* x0s = (float*)(smem + OFF_X0);
    float* w0s = (float*)(smem + OFF_W0);
    float* w1s = (float*)(smem + OFF_W1);
    float* h0s = (float*)(smem + OFF_H0);
    float* h1s = (float*)(smem + OFF_H1);
    float* nfs = (float*)(smem + OFF_NF);
    float* shs = (float*)(smem + OFF_SH);
    int* idxs  = (int*)(smem + OFF_IDX);
    __nv_bfloat16* Yh = (__nv_bfloat16*)(smem + OFF_W0);           // 32x136, w0s dead
    __nv_bfloat16* Yl = (__nv_bfloat16*)(smem + OFF_W0 + 8704);
    __nv_bfloat16* Hh = (__nv_bfloat16*)(smem + OFF_H0);           // 32x72
    __nv_bfloat16* Hl = (__nv_bfloat16*)(smem + OFF_H0 + 4608);

    int tid = threadIdx.x;
    int n = blockIdx.x, eg0 = n * 32;

    // ---- stage ----
    if (tid < 32) idxs[tid] = sp_idx[eg0 + tid];
    for (int i = tid; i < NROWS * 128; i += NTH)
        nfs[i] = g_node[(size_t)n * NROWS * 128 + i];
    for (int i = tid; i < 32 * 128; i += NTH) {
        int e = i >> 7, c = i & 127;
        x0s[e * 132 + c] = x_edge[(size_t)(eg0 + e) * 128 + c];
    }
    for (int i = tid; i < 64 * 128; i += NTH) {
        int o = i >> 7, c = i & 127;
        w0s[o * 132 + c] = __ldg(&w0[o * 128 + c]);
    }
    for (int i = tid; i < 64 * 64; i += NTH) {
        int o = i >> 6, c = i & 63;
        w1s[o * 68 + c] = __ldg(&w1[o * 64 + c]);
    }
    if (tid < 32) {
        const float* ev = edge_vec + (size_t)(eg0 + tid) * 3;
        float x = ev[0], y = ev[1], z = ev[2];
        float inv = 1.f / fmaxf(sqrtf(x * x + y * y + z * z), 1e-12f);
        x *= inv; y *= inv; z *= inv;
        float* s = shs + tid * 12;
        const float C0 = 0.28209479177387814f, C1 = 0.4886025119029199f;
        const float C2 = 0.6307831305050401f, S3 = 1.7320508075688772f;
        s[0] = C0; s[1] = C1 * x; s[2] = C1 * y; s[3] = C1 * z;
        s[4] = C2 * S3 * x * z; s[5] = C2 * S3 * x * y;
        s[6] = C2 * (y * y - 0.5f * (x * x + z * z)); s[7] = C2 * S3 * y * z;
        s[8] = C2 * 0.5f * S3 * (z * z - x * x);
    }
    __syncthreads();

    int tx = tid & 15, ty = tid >> 4;
    int e2 = ty * 2;

    // ---- rad0: 32e x 64o, k=128; o = tx + 16j (2-way banks) ----
    {
        float a[2][4];
#pragma unroll
        for (int j = 0; j < 4; j++) {
            float bv = __ldg(&b0[tx + 16 * j]);
            a[0][j] = bv; a[1][j] = bv;
        }
#pragma unroll 4
        for (int k4 = 0; k4 < 32; k4++) {
            float4 xv[2], wv[4];
#pragma unroll
            for (int i = 0; i < 2; i++) xv[i] = *(const float4*)&x0s[(e2 + i) * 132 + k4 * 4];
#pragma unroll
            for (int j = 0; j < 4; j++) wv[j] = *(const float4*)&w0s[(tx + 16 * j) * 132 + k4 * 4];
#pragma unroll
            for (int i = 0; i < 2; i++)
#pragma unroll
                for (int j = 0; j < 4; j++)
                    a[i][j] += xv[i].x*wv[j].x + xv[i].y*wv[j].y + xv[i].z*wv[j].z + xv[i].w*wv[j].w;
        }
#pragma unroll
        for (int i = 0; i < 2; i++)
#pragma unroll
            for (int j = 0; j < 4; j++)
                h0s[(e2 + i) * 68 + tx + 16 * j] = a[i][j];
    }
    __syncthreads();
    {   // LN+SiLU h0 (8 threads/edge)
        int e = tid >> 3, p = tid & 7;
        float* row = h0s + e * 68 + p * 8;
        float v[8], s1 = 0.f, s2 = 0.f;
#pragma unroll
        for (int i = 0; i < 8; i++) { v[i] = row[i]; s1 += v[i]; s2 += v[i]*v[i]; }
        s1 += __shfl_xor_sync(~0u, s1, 1); s2 += __shfl_xor_sync(~0u, s2, 1);
        s1 += __shfl_xor_sync(~0u, s1, 2); s2 += __shfl_xor_sync(~0u, s2, 2);
        s1 += __shfl_xor_sync(~0u, s1, 4); s2 += __shfl_xor_sync(~0u, s2, 4);
        float mean = s1 * (1.f/64.f), var = s2 * (1.f/64.f) - mean*mean;
        float rs = rsqrtf(var + 1e-5f);
#pragma unroll
        for (int i = 0; i < 8; i++) {
            float z = (v[i] - mean) * rs * __ldg(&g0[p*8+i]) + __ldg(&bb0[p*8+i]);
            row[i] = z / (1.f + expf(-z));
        }
    }
    __syncthreads();
    // ---- rad1: 32e x 64o, k=64; o = tx + 16j ----
    {
        float a[2][4];
#pragma unroll
        for (int j = 0; j < 4; j++) {
            float bv = __ldg(&b1[tx + 16 * j]);
            a[0][j] = bv; a[1][j] = bv;
        }
#pragma unroll 4
        for (int k4 = 0; k4 < 16; k4++) {
            float4 xv[2], wv[4];
#pragma unroll
            for (int i = 0; i < 2; i++) xv[i] = *(const float4*)&h0s[(e2 + i) * 68 + k4 * 4];
#pragma unroll
            for (int j = 0; j < 4; j++) wv[j] = *(const float4*)&w1s[(tx + 16 * j) * 68 + k4 * 4];
#pragma unroll
            for (int i = 0; i < 2; i++)
#pragma unroll
                for (int j = 0; j < 4; j++)
                    a[i][j] += xv[i].x*wv[j].x + xv[i].y*wv[j].y + xv[i].z*wv[j].z + xv[i].w*wv[j].w;
        }
#pragma unroll
        for (int i = 0; i < 2; i++)
#pragma unroll
            for (int j = 0; j < 4; j++)
                h1s[(e2 + i) * 68 + tx + 16 * j] = a[i][j];
    }
    __syncthreads();   // rad1's h0s reads done; h0s region free for H
    {   // LN+SiLU h1 -> split -> Hh/Hl
        int e = tid >> 3, p = tid & 7;
        const float* row = h1s + e * 68 + p * 8;
        float v[8], s1 = 0.f, s2 = 0.f;
#pragma unroll
        for (int i = 0; i < 8; i++) { v[i] = row[i]; s1 += v[i]; s2 += v[i]*v[i]; }
        s1 += __shfl_xor_sync(~0u, s1, 1); s2 += __shfl_xor_sync(~0u, s2, 1);
        s1 += __shfl_xor_sync(~0u, s1, 2); s2 += __shfl_xor_sync(~0u, s2, 2);
        s1 += __shfl_xor_sync(~0u, s1, 4); s2 += __shfl_xor_sync(~0u, s2, 4);
        float mean = s1 * (1.f/64.f), var = s2 * (1.f/64.f) - mean*mean;
        float rs = rsqrtf(var + 1e-5f);
#pragma unroll
        for (int i = 0; i < 8; i++) {
            float z = (v[i] - mean) * rs * __ldg(&g1[p*8+i]) + __ldg(&bb1[p*8+i]);
            float sil = z / (1.f + expf(-z));
            __nv_bfloat16 hi, lo;
            split_bf16(sil, hi, lo);
            Hh[e * 72 + p * 8 + i] = hi;
            Hl[e * 72 + p * 8 + i] = lo;
        }
    }
    __syncthreads();

    // ---- warp roles ----
    int lane = tid & 31, w = tid >> 5;
    int we = w & 1,  jg = w >> 1;        // w2: e we*16, j jg*32
    int weF = w & 1, wnF = w >> 1;       // FC: e weF*16, n wnF*64
    int g = lane >> 3, r = lane & 7;
    int h_row = r + ((g & 1) << 3), h_col = (g >> 1) << 3;
    int e_lo = lane >> 2, q = lane & 3;

    float acc[4][2][4];                  // FC accum: [nt'][n8][frag]
#pragma unroll
    for (int a1 = 0; a1 < 4; a1++)
#pragma unroll
        for (int a2 = 0; a2 < 2; a2++)
#pragma unroll
            for (int a3 = 0; a3 < 4; a3++) acc[a1][a2][a3] = 0.f;

    for (int b = 0; b < 6; b++) {
        // ---- x0 gather ----
        for (int i = tid; i < 32 * 128; i += NTH) {
            int e = i >> 7, d = i & 127;
            const float* s = shs + e * 12;
            const float* src = (b & 1) ? g_node + (size_t)idxs[e] * (NROWS * 128) : nfs;
            float x0;
            if      (b < 2) x0 = s[0] * src[d];
            else if (b < 4) x0 = s[1]*src[128+d] + s[2]*src[256+d] + s[3]*src[384+d];
            else            x0 = s[4]*src[512+d] + s[5]*src[640+d] + s[6]*src[768+d]
                               + s[7]*src[896+d] + s[8]*src[1024+d];
            x0s[e * 132 + d] = x0;
        }
        __syncthreads();                               // S1: x0 visible

        // ---- w2-mma: 16e x 32j over 64k, B-frags via LDG ----
        float acc2[2][2][4];
#pragma unroll
        for (int jt = 0; jt < 2; jt++)
#pragma unroll
            for (int n8 = 0; n8 < 2; n8++)
#pragma unroll
                for (int c = 0; c < 4; c++) acc2[jt][n8][c] = 0.f;
#pragma unroll
        for (int kk = 0; kk < 4; kk++) {
            uint32_t ah[4], al[4];
            ldmx4(sptr(&Hh[(we * 16 + h_row) * 72 + kk * 16 + h_col]), ah[0], ah[1], ah[2], ah[3]);
            ldmx4(sptr(&Hl[(we * 16 + h_row) * 72 + kk * 16 + h_col]), al[0], al[1], al[2], al[3]);
#pragma unroll
            for (int jt = 0; jt < 2; jt++) {
                size_t ti = ((((size_t)b * 8 + jg * 2 + jt) * 4 + kk) * 32 + lane) * 4;
                uint4 bh = __ldg((const uint4*)&g_w2p[0][ti]);
                uint4 bl = __ldg((const uint4*)&g_w2p[1][ti]);
#pragma unroll
                for (int n8 = 0; n8 < 2; n8++) {
                    const uint32_t* bhp = n8 ? &bh.z : &bh.x;
                    const uint32_t* blp = n8 ? &bl.z : &bl.x;
                    float* c = acc2[jt][n8];
                    mma16816(c, ah, bhp);
                    mma16816(c, al, bhp);
                    mma16816(c, ah, blp);
                }
            }
        }

        // ---- y = x0*(m0+b2) -> Yh/Yl (own region; x0 read inline) ----
#pragma unroll
        for (int jt = 0; jt < 2; jt++) {
#pragma unroll
            for (int n8 = 0; n8 < 2; n8++) {
                int jl = jg * 32 + jt * 16 + n8 * 8 + 2 * q;
                int jgl = b * 128 + jl;
                float b20 = __ldg(&b2[jgl]), b21 = __ldg(&b2[jgl + 1]);
#pragma unroll
                for (int ri = 0; ri < 2; ri++) {
                    int e = we * 16 + e_lo + ri * 8;
                    float2 xv = *(const float2*)&x0s[e * 132 + jl];
                    float y0 = xv.x * (acc2[jt][n8][ri * 2]     + b20);
                    float y1 = xv.y * (acc2[jt][n8][ri * 2 + 1] + b21);
                    __nv_bfloat16 h0b, l0b, h1b, l1b;
                    split_bf16(y0, h0b, l0b); split_bf16(y1, h1b, l1b);
                    *(__nv_bfloat162*)&Yh[e * 136 + jl] = __nv_bfloat162(h0b, h1b);
                    *(__nv_bfloat162*)&Yl[e * 136 + jl] = __nv_bfloat162(l0b, l1b);
                }
            }
        }
        __syncthreads();                               // S2: Y visible

        // ---- FC: 16e x 64n over 128k, B-frags via LDG ----
#pragma unroll
        for (int kt = 0; kt < 8; kt++) {
            uint32_t ah[4], al[4];
            ldmx4(sptr(&Yh[(weF * 16 + h_row) * 136 + kt * 16 + h_col]), ah[0], ah[1], ah[2], ah[3]);
            ldmx4(sptr(&Yl[(weF * 16 + h_row) * 136 + kt * 16 + h_col]), al[0], al[1], al[2], al[3]);
#pragma unroll
            for (int nt = 0; nt < 4; nt++) {
                size_t ti = ((((size_t)b * 16 + wnF * 4 + nt) * 8 + kt) * 32 + lane) * 4;
                uint4 bh = __ldg((const uint4*)&g_fcp[0][ti]);
                uint4 bl = __ldg((const uint4*)&g_fcp[1][ti]);
#pragma unroll
                for (int n8 = 0; n8 < 2; n8++) {
                    const uint32_t* bhp = n8 ? &bh.z : &bh.x;
                    const uint32_t* blp = n8 ? &bl.z : &bl.x;
                    float* c = acc[nt][n8];
                    mma16816(c, ah, bhp);
                    mma16816(c, al, bhp);
                    mma16816(c, ah, blp);
                }
            }
        }
        // no sync needed: next gather (x0s) is not read by FC; next Y-write is behind next S1
    }

    // ---- epilogue: warp (weF, wnF): rows weF*16.., heads wnF*2 + ht ----
#pragma unroll
    for (int ht = 0; ht < 2; ht++) {
        int head = wnF * 2 + ht;
#pragma unroll
        for (int ri = 0; ri < 2; ri++) {
            int erow = eg0 + weF * 16 + e_lo + ri * 8;
            float v[8], s1 = 0.f, s2 = 0.f;
#pragma unroll
            for (int ntl = 0; ntl < 2; ntl++)
#pragma unroll
                for (int n8 = 0; n8 < 2; n8++)
#pragma unroll
                    for (int c = 0; c < 2; c++) {
                        int d = ntl * 16 + n8 * 8 + 2 * q + c;
                        float val = acc[ht * 2 + ntl][n8][ri * 2 + c] + __ldg(&fc_b[head * 32 + d]);
                        v[ntl * 4 + n8 * 2 + c] = val;
                        s1 += val; s2 += val * val;
                    }
            s1 += __shfl_xor_sync(~0u, s1, 1); s2 += __shfl_xor_sync(~0u, s2, 1);
            s1 += __shfl_xor_sync(~0u, s1, 2); s2 += __shfl_xor_sync(~0u, s2, 2);
            float mean = s1 * (1.f / 32.f), var = s2 * (1.f / 32.f) - mean * mean;
            float rs = rsqrtf(var + 1e-5f);
            float p = 0.f;
#pragma unroll
            for (int j = 0; j < 8; j++) {
                int ntl = j >> 2, n8 = (j >> 1) & 1, c = j & 1;
                int d = ntl * 16 + n8 * 8 + 2 * q + c;
                float z = (v[j] - mean) * rs * __ldg(&ln_g[d]) + __ldg(&ln_b[d]);
                float sg = 1.f / (1.f + expf(-z));
                float slr = 0.6f * z + 0.4f * z * (2.f * sg - 1.f);
                p += slr * __ldg(&alpha_dot[head * 32 + d]);
            }
            p += __shfl_xor_sync(~0u, p, 1);
            p += __shfl_xor_sync(~0u, p, 2);
            if (q == 0)
                out[(size_t)erow * 8 + head] = p;
        }
    }
}

// ============ launch ============
extern "C" void kernel_launch(void* const* d_in, const int* in_sizes, int n_in,
                              void* d_out, int out_size) {
    const float* x_edge   = (const float*)d_in[0];
    const float* node_in  = (const float*)d_in[1];
    const float* edge_vec = (const float*)d_in[2];
    const int*   sp       = (const int*)d_in[3];
    const float* dot_w    = (const float*)d_in[4];
    const float* dot_b    = (const float*)d_in[5];
    const float* w0  = (const float*)d_in[6];
    const float* b0  = (const float*)d_in[7];
    const float* w1  = (const float*)d_in[8];
    const float* b1  = (const float*)d_in[9];
    const float* w2  = (const float*)d_in[10];
    const float* b2  = (const float*)d_in[11];
    const float* g0  = (const float*)d_in[12];
    const float* bb0 = (const float*)d_in[13];
    const float* g1  = (const float*)d_in[14];
    const float* bb1 = (const float*)d_in[15];
    const float* fcw = (const float*)d_in[16];
    const float* fcb = (const float*)d_in[17];
    const float* lng = (const float*)d_in[18];
    const float* lnb = (const float*)d_in[19];
    const float* ad  = (const float*)d_in[20];
    float* out = (float*)d_out;

    k01<<<NN, 256>>>(node_in, dot_w, dot_b, w2, fcw);

    cudaFuncSetAttribute(k2, cudaFuncAttributeMaxDynamicSharedMemorySize, SMEM_B);
    k2<<<NN, NTH, SMEM_B>>>(x_edge, edge_vec, sp,
                            w0, b0, w1, b1, b2, g0, bb0, g1, bb1,
                            fcb, lng, lnb, ad, out);
}

// round 16
// speedup vs baseline: 1.4708x; 1.0313x over previous
#include <cuda_runtime.h>
#include <cuda_bf16.h>
#include <math.h>
#include <stdint.h>

#define NN 8192
#define NROWS 9
#define RAD3 768
#define NTH 256

__device__ float g_node[(size_t)NN * NROWS * 128];
// pre-packed B-fragments (bf16x2 words), [plane 0=hi,1=lo]
__device__ __align__(16) uint32_t g_w2p[2][6 * 8 * 4 * 32 * 4];     // [b][jt][kt][lane][j]
__device__ __align__(16) uint32_t g_fcp[2][6 * 16 * 8 * 32 * 4];    // [b][nt][kt][lane][j]

__device__ __forceinline__ void split_bf16(float v, __nv_bfloat16& hi, __nv_bfloat16& lo) {
    hi = __float2bfloat16(v);
    lo = __float2bfloat16(v - __bfloat162float(hi));
}

// ============ K01: node projection + fragment pre-pack ============
__global__ void k01(const float* __restrict__ node_in, const float* __restrict__ dot_w,
                    const float* __restrict__ dot_b, const float* __restrict__ w2,
                    const float* __restrict__ fcw) {
    int gt = blockIdx.x * 256 + threadIdx.x;
    if (gt < 24576) {                                  // w2 frag pack
        int j = gt & 3, l = (gt >> 2) & 31, kt = (gt >> 7) & 3;
        int jt = (gt >> 9) & 7, b = gt >> 12;
        int jg = b * 128 + jt * 16 + ((j >> 1) << 3) + (l >> 2);
        int k  = kt * 16 + ((j & 1) << 3) + ((l & 3) << 1);
        float v0 = w2[(size_t)jg * 64 + k], v1 = w2[(size_t)jg * 64 + k + 1];
        __nv_bfloat16 h0, l0, h1, l1;
        split_bf16(v0, h0, l0); split_bf16(v1, h1, l1);
        __nv_bfloat162 ph(h0, h1), pl(l0, l1);
        g_w2p[0][gt] = *(uint32_t*)&ph;
        g_w2p[1][gt] = *(uint32_t*)&pl;
    } else if (gt < 24576 + 98304) {                   // fc frag pack
        int i = gt - 24576;
        int j = i & 3, l = (i >> 2) & 31, kt = (i >> 7) & 7;
        int nt = (i >> 10) & 15, b = i >> 14;
        int n = nt * 16 + ((j >> 1) << 3) + (l >> 2);
        int k = b * 128 + kt * 16 + ((j & 1) << 3) + ((l & 3) << 1);
        float v0 = fcw[(size_t)n * RAD3 + k], v1 = fcw[(size_t)n * RAD3 + k + 1];
        __nv_bfloat16 h0, l0, h1, l1;
        split_bf16(v0, h0, l0); split_bf16(v1, h1, l1);
        __nv_bfloat162 ph(h0, h1), pl(l0, l1);
        g_fcp[0][i] = *(uint32_t*)&ph;
        g_fcp[1][i] = *(uint32_t*)&pl;
    }
    __shared__ __align__(16) float sm[NROWS * 128];
    int n = blockIdx.x;
    const float* src = node_in + (size_t)n * NROWS * 128;
    for (int i = threadIdx.x; i < NROWS * 128; i += blockDim.x) sm[i] = src[i];
    __syncthreads();
    for (int idx = threadIdx.x; idx < NROWS * 128; idx += blockDim.x) {
        int m = idx >> 7, d = idx & 127;
        int l = (m == 0) ? 0 : (m < 4 ? 1 : 2);
        const float4* w = (const float4*)(dot_w + (size_t)l * 16384 + (size_t)d * 128);
        const float4* x = (const float4*)(sm + m * 128);
        float acc = (m == 0) ? dot_b[d] : 0.f;
#pragma unroll
        for (int c4 = 0; c4 < 32; c4++) {
            float4 wv = __ldg(&w[c4]); float4 xv = x[c4];
            acc += wv.x * xv.x + wv.y * xv.y + wv.z * xv.z + wv.w * xv.w;
        }
        g_node[(size_t)n * NROWS * 128 + idx] = acc;
    }
}

// ============ helpers ============
__device__ __forceinline__ uint32_t sptr(const void* p) {
    return (uint32_t)__cvta_generic_to_shared(p);
}
__device__ __forceinline__ void ldmx4(uint32_t a, uint32_t& r0, uint32_t& r1,
                                      uint32_t& r2, uint32_t& r3) {
    asm volatile("ldmatrix.sync.aligned.m8n8.x4.shared.b16 {%0,%1,%2,%3}, [%4];"
                 : "=r"(r0), "=r"(r1), "=r"(r2), "=r"(r3) : "r"(a));
}
__device__ __forceinline__ void mma16816(float* c, const uint32_t* a, const uint32_t* b) {
    asm volatile("mma.sync.aligned.m16n8k16.row.col.f32.bf16.bf16.f32 "
                 "{%0,%1,%2,%3}, {%4,%5,%6,%7}, {%8,%9}, {%0,%1,%2,%3};"
                 : "+f"(c[0]), "+f"(c[1]), "+f"(c[2]), "+f"(c[3])
                 : "r"(a[0]), "r"(a[1]), "r"(a[2]), "r"(a[3]), "r"(b[0]), "r"(b[1]));
}

// ============ smem layout (bytes) ============
#define OFF_X0  0          // 16896: xs / x0 chunk (32x132 f)
#define OFF_W0  16896      // 33792: w0s (64x132 f) | Yh (32x136 bf16)+Yl after prologue
#define OFF_W1  50688      // 17408: w1s (64x68 f)
#define OFF_H0  68096      // 9216: h0s (32x68 f) | Hh/Hl (32x72 bf16)
#define OFF_H1  77312      // 8704: h1s (32x68 f)
#define OFF_NF  86016      // 4608
#define OFF_SH  90624      // 1536
#define OFF_IDX 92160      // 128
#define SMEM_B  92288

// ============ K2: 32 edges/block ============
__global__ void __launch_bounds__(NTH, 2) k2(
    const float* __restrict__ x_edge, const float* __restrict__ edge_vec,
    const int* __restrict__ sp_idx,
    const float* __restrict__ w0, const float* __restrict__ b0,
    const float* __restrict__ w1, const float* __restrict__ b1,
    const float* __restrict__ b2,
    const float* __restrict__ g0, const float* __restrict__ bb0,
    const float* __restrict__ g1, const float* __restrict__ bb1,
    const float* __restrict__ fc_b,
    const float* __restrict__ ln_g, const float* __restrict__ ln_b,
    const float* __restrict__ alpha_dot, float* __restrict__ out)
{
    extern __shared__ __align__(16) char smem[];
    float* x0s = (float*)(smem + OFF_X0);
    float* w0s = (float*)(smem + OFF_W0);
    float* w1s = (float*)(smem + OFF_W1);
    float* h0s = (float*)(smem + OFF_H0);
    float* h1s = (float*)(smem + OFF_H1);
    float* nfs = (float*)(smem + OFF_NF);
    float* shs = (float*)(smem + OFF_SH);
    int* idxs  = (int*)(smem + OFF_IDX);
    __nv_bfloat16* Yh = (__nv_bfloat16*)(smem + OFF_W0);           // 32x136, w0s dead
    __nv_bfloat16* Yl = (__nv_bfloat16*)(smem + OFF_W0 + 8704);
    __nv_bfloat16* Hh = (__nv_bfloat16*)(smem + OFF_H0);           // 32x72
    __nv_bfloat16* Hl = (__nv_bfloat16*)(smem + OFF_H0 + 4608);

    int tid = threadIdx.x;
    int n = blockIdx.x, eg0 = n * 32;

    // ---- stage ----
    if (tid < 32) idxs[tid] = sp_idx[eg0 + tid];
    for (int i = tid; i < NROWS * 128; i += NTH)
        nfs[i] = g_node[(size_t)n * NROWS * 128 + i];
    for (int i = tid; i < 32 * 128; i += NTH) {
        int e = i >> 7, c = i & 127;
        x0s[e * 132 + c] = x_edge[(size_t)(eg0 + e) * 128 + c];
    }
    for (int i = tid; i < 64 * 128; i += NTH) {
        int o = i >> 7, c = i & 127;
        w0s[o * 132 + c] = __ldg(&w0[o * 128 + c]);
    }
    for (int i = tid; i < 64 * 64; i += NTH) {
        int o = i >> 6, c = i & 63;
        w1s[o * 68 + c] = __ldg(&w1[o * 64 + c]);
    }
    if (tid < 32) {
        const float* ev = edge_vec + (size_t)(eg0 + tid) * 3;
        float x = ev[0], y = ev[1], z = ev[2];
        float inv = 1.f / fmaxf(sqrtf(x * x + y * y + z * z), 1e-12f);
        x *= inv; y *= inv; z *= inv;
        float* s = shs + tid * 12;
        const float C0 = 0.28209479177387814f, C1 = 0.4886025119029199f;
        const float C2 = 0.6307831305050401f, S3 = 1.7320508075688772f;
        s[0] = C0; s[1] = C1 * x; s[2] = C1 * y; s[3] = C1 * z;
        s[4] = C2 * S3 * x * z; s[5] = C2 * S3 * x * y;
        s[6] = C2 * (y * y - 0.5f * (x * x + z * z)); s[7] = C2 * S3 * y * z;
        s[8] = C2 * 0.5f * S3 * (z * z - x * x);
    }
    __syncthreads();

    int tx = tid & 15, ty = tid >> 4;
    int e2 = ty * 2;

    // ---- rad0: 32e x 64o, k=128; o = tx + 16j (2-way banks) ----
    {
        float a[2][4];
#pragma unroll
        for (int j = 0; j < 4; j++) {
            float bv = __ldg(&b0[tx + 16 * j]);
            a[0][j] = bv; a[1][j] = bv;
        }
#pragma unroll 4
        for (int k4 = 0; k4 < 32; k4++) {
            float4 xv[2], wv[4];
#pragma unroll
            for (int i = 0; i < 2; i++) xv[i] = *(const float4*)&x0s[(e2 + i) * 132 + k4 * 4];
#pragma unroll
            for (int j = 0; j < 4; j++) wv[j] = *(const float4*)&w0s[(tx + 16 * j) * 132 + k4 * 4];
#pragma unroll
            for (int i = 0; i < 2; i++)
#pragma unroll
                for (int j = 0; j < 4; j++)
                    a[i][j] += xv[i].x*wv[j].x + xv[i].y*wv[j].y + xv[i].z*wv[j].z + xv[i].w*wv[j].w;
        }
#pragma unroll
        for (int i = 0; i < 2; i++)
#pragma unroll
            for (int j = 0; j < 4; j++)
                h0s[(e2 + i) * 68 + tx + 16 * j] = a[i][j];
    }
    __syncthreads();
    {   // LN+SiLU h0 (8 threads/edge)
        int e = tid >> 3, p = tid & 7;
        float* row = h0s + e * 68 + p * 8;
        float v[8], s1 = 0.f, s2 = 0.f;
#pragma unroll
        for (int i = 0; i < 8; i++) { v[i] = row[i]; s1 += v[i]; s2 += v[i]*v[i]; }
        s1 += __shfl_xor_sync(~0u, s1, 1); s2 += __shfl_xor_sync(~0u, s2, 1);
        s1 += __shfl_xor_sync(~0u, s1, 2); s2 += __shfl_xor_sync(~0u, s2, 2);
        s1 += __shfl_xor_sync(~0u, s1, 4); s2 += __shfl_xor_sync(~0u, s2, 4);
        float mean = s1 * (1.f/64.f), var = s2 * (1.f/64.f) - mean*mean;
        float rs = rsqrtf(var + 1e-5f);
#pragma unroll
        for (int i = 0; i < 8; i++) {
            float z = (v[i] - mean) * rs * __ldg(&g0[p*8+i]) + __ldg(&bb0[p*8+i]);
            row[i] = z / (1.f + expf(-z));
        }
    }
    __syncthreads();
    // ---- rad1: 32e x 64o, k=64; o = tx + 16j ----
    {
        float a[2][4];
#pragma unroll
        for (int j = 0; j < 4; j++) {
            float bv = __ldg(&b1[tx + 16 * j]);
            a[0][j] = bv; a[1][j] = bv;
        }
#pragma unroll 4
        for (int k4 = 0; k4 < 16; k4++) {
            float4 xv[2], wv[4];
#pragma unroll
            for (int i = 0; i < 2; i++) xv[i] = *(const float4*)&h0s[(e2 + i) * 68 + k4 * 4];
#pragma unroll
            for (int j = 0; j < 4; j++) wv[j] = *(const float4*)&w1s[(tx + 16 * j) * 68 + k4 * 4];
#pragma unroll
            for (int i = 0; i < 2; i++)
#pragma unroll
                for (int j = 0; j < 4; j++)
                    a[i][j] += xv[i].x*wv[j].x + xv[i].y*wv[j].y + xv[i].z*wv[j].z + xv[i].w*wv[j].w;
        }
#pragma unroll
        for (int i = 0; i < 2; i++)
#pragma unroll
            for (int j = 0; j < 4; j++)
                h1s[(e2 + i) * 68 + tx + 16 * j] = a[i][j];
    }
    __syncthreads();   // rad1's h0s reads done; h0s region free for H
    {   // LN+SiLU h1 -> split -> Hh/Hl
        int e = tid >> 3, p = tid & 7;
        const float* row = h1s + e * 68 + p * 8;
        float v[8], s1 = 0.f, s2 = 0.f;
#pragma unroll
        for (int i = 0; i < 8; i++) { v[i] = row[i]; s1 += v[i]; s2 += v[i]*v[i]; }
        s1 += __shfl_xor_sync(~0u, s1, 1); s2 += __shfl_xor_sync(~0u, s2, 1);
        s1 += __shfl_xor_sync(~0u, s1, 2); s2 += __shfl_xor_sync(~0u, s2, 2);
        s1 += __shfl_xor_sync(~0u, s1, 4); s2 += __shfl_xor_sync(~0u, s2, 4);
        float mean = s1 * (1.f/64.f), var = s2 * (1.f/64.f) - mean*mean;
        float rs = rsqrtf(var + 1e-5f);
#pragma unroll
        for (int i = 0; i < 8; i++) {
            float z = (v[i] - mean) * rs * __ldg(&g1[p*8+i]) + __ldg(&bb1[p*8+i]);
            float sil = z / (1.f + expf(-z));
            __nv_bfloat16 hi, lo;
            split_bf16(sil, hi, lo);
            Hh[e * 72 + p * 8 + i] = hi;
            Hl[e * 72 + p * 8 + i] = lo;
        }
    }
    __syncthreads();

    // ---- warp roles: warp w owns j-group w (w2) and head w (FC) ----
    int lane = tid & 31, w = tid >> 5;
    int g = lane >> 3, r = lane & 7;
    int h_row = r + ((g & 1) << 3), h_col = (g >> 1) << 3;
    int e_lo = lane >> 2, q = lane & 3;

    float acc[2][2][2][4];               // FC accum: [et][ntl][n8][frag]
#pragma unroll
    for (int a0 = 0; a0 < 2; a0++)
#pragma unroll
        for (int a1 = 0; a1 < 2; a1++)
#pragma unroll
            for (int a2 = 0; a2 < 2; a2++)
#pragma unroll
                for (int a3 = 0; a3 < 4; a3++) acc[a0][a1][a2][a3] = 0.f;

    for (int b = 0; b < 6; b++) {
        // ---- x0 gather ----
        for (int i = tid; i < 32 * 128; i += NTH) {
            int e = i >> 7, d = i & 127;
            const float* s = shs + e * 12;
            const float* src = (b & 1) ? g_node + (size_t)idxs[e] * (NROWS * 128) : nfs;
            float x0;
            if      (b < 2) x0 = s[0] * src[d];
            else if (b < 4) x0 = s[1]*src[128+d] + s[2]*src[256+d] + s[3]*src[384+d];
            else            x0 = s[4]*src[512+d] + s[5]*src[640+d] + s[6]*src[768+d]
                               + s[7]*src[896+d] + s[8]*src[1024+d];
            x0s[e * 132 + d] = x0;
        }
        __syncthreads();                               // S1: x0 visible

        // ---- w2-mma: warp tile 32e x 16j over 64k (jt = w) ----
        float acc2[2][2][4];                            // [et][n8][frag]
#pragma unroll
        for (int et = 0; et < 2; et++)
#pragma unroll
            for (int n8 = 0; n8 < 2; n8++)
#pragma unroll
                for (int c = 0; c < 4; c++) acc2[et][n8][c] = 0.f;
#pragma unroll
        for (int kk = 0; kk < 4; kk++) {
            uint32_t ah[2][4], al[2][4];
#pragma unroll
            for (int et = 0; et < 2; et++) {
                ldmx4(sptr(&Hh[(et * 16 + h_row) * 72 + kk * 16 + h_col]), ah[et][0], ah[et][1], ah[et][2], ah[et][3]);
                ldmx4(sptr(&Hl[(et * 16 + h_row) * 72 + kk * 16 + h_col]), al[et][0], al[et][1], al[et][2], al[et][3]);
            }
            size_t ti = ((((size_t)b * 8 + w) * 4 + kk) * 32 + lane) * 4;
            uint4 bh = __ldg((const uint4*)&g_w2p[0][ti]);
            uint4 bl = __ldg((const uint4*)&g_w2p[1][ti]);
#pragma unroll
            for (int et = 0; et < 2; et++)
#pragma unroll
                for (int n8 = 0; n8 < 2; n8++) {
                    const uint32_t* bhp = n8 ? &bh.z : &bh.x;
                    const uint32_t* blp = n8 ? &bl.z : &bl.x;
                    float* c = acc2[et][n8];
                    mma16816(c, ah[et], bhp);
                    mma16816(c, al[et], bhp);
                    mma16816(c, ah[et], blp);
                }
        }

        // ---- y = x0*(m0+b2) -> Yh/Yl ----
#pragma unroll
        for (int n8 = 0; n8 < 2; n8++) {
            int jl = w * 16 + n8 * 8 + 2 * q;
            int jgl = b * 128 + jl;
            float b20 = __ldg(&b2[jgl]), b21 = __ldg(&b2[jgl + 1]);
#pragma unroll
            for (int et = 0; et < 2; et++)
#pragma unroll
                for (int ri = 0; ri < 2; ri++) {
                    int e = et * 16 + e_lo + ri * 8;
                    float2 xv = *(const float2*)&x0s[e * 132 + jl];
                    float y0 = xv.x * (acc2[et][n8][ri * 2]     + b20);
                    float y1 = xv.y * (acc2[et][n8][ri * 2 + 1] + b21);
                    __nv_bfloat16 h0b, l0b, h1b, l1b;
                    split_bf16(y0, h0b, l0b); split_bf16(y1, h1b, l1b);
                    *(__nv_bfloat162*)&Yh[e * 136 + jl] = __nv_bfloat162(h0b, h1b);
                    *(__nv_bfloat162*)&Yl[e * 136 + jl] = __nv_bfloat162(l0b, l1b);
                }
        }
        __syncthreads();                               // S2: Y visible

        // ---- FC: warp tile 32e x 32n over 128k (head = w, nt = w*2+ntl) ----
#pragma unroll
        for (int kt = 0; kt < 8; kt++) {
            uint32_t ah[2][4], al[2][4];
#pragma unroll
            for (int et = 0; et < 2; et++) {
                ldmx4(sptr(&Yh[(et * 16 + h_row) * 136 + kt * 16 + h_col]), ah[et][0], ah[et][1], ah[et][2], ah[et][3]);
                ldmx4(sptr(&Yl[(et * 16 + h_row) * 136 + kt * 16 + h_col]), al[et][0], al[et][1], al[et][2], al[et][3]);
            }
#pragma unroll
            for (int ntl = 0; ntl < 2; ntl++) {
                size_t ti = ((((size_t)b * 16 + w * 2 + ntl) * 8 + kt) * 32 + lane) * 4;
                uint4 bh = __ldg((const uint4*)&g_fcp[0][ti]);
                uint4 bl = __ldg((const uint4*)&g_fcp[1][ti]);
#pragma unroll
                for (int et = 0; et < 2; et++)
#pragma unroll
                    for (int n8 = 0; n8 < 2; n8++) {
                        const uint32_t* bhp = n8 ? &bh.z : &bh.x;
                        const uint32_t* blp = n8 ? &bl.z : &bl.x;
                        float* c = acc[et][ntl][n8];
                        mma16816(c, ah[et], bhp);
                        mma16816(c, al[et], bhp);
                        mma16816(c, ah[et], blp);
                    }
            }
        }
        // no sync: next gather writes x0s only; next Y-write is behind next S1
    }

    // ---- epilogue: warp w = head w; rows et*16 + e_lo + ri*8 ----
    int head = w;
#pragma unroll
    for (int et = 0; et < 2; et++) {
#pragma unroll
        for (int ri = 0; ri < 2; ri++) {
            int erow = eg0 + et * 16 + e_lo + ri * 8;
            float v[8], s1 = 0.f, s2 = 0.f;
#pragma unroll
            for (int ntl = 0; ntl < 2; ntl++)
#pragma unroll
                for (int n8 = 0; n8 < 2; n8++)
#pragma unroll
                    for (int c = 0; c < 2; c++) {
                        int d = ntl * 16 + n8 * 8 + 2 * q + c;
                        float val = acc[et][ntl][n8][ri * 2 + c] + __ldg(&fc_b[head * 32 + d]);
                        v[ntl * 4 + n8 * 2 + c] = val;
                        s1 += val; s2 += val * val;
                    }
            s1 += __shfl_xor_sync(~0u, s1, 1); s2 += __shfl_xor_sync(~0u, s2, 1);
            s1 += __shfl_xor_sync(~0u, s1, 2); s2 += __shfl_xor_sync(~0u, s2, 2);
            float mean = s1 * (1.f / 32.f), var = s2 * (1.f / 32.f) - mean * mean;
            float rs = rsqrtf(var + 1e-5f);
            float p = 0.f;
#pragma unroll
            for (int j = 0; j < 8; j++) {
                int ntl = j >> 2, n8 = (j >> 1) & 1, c = j & 1;
                int d = ntl * 16 + n8 * 8 + 2 * q + c;
                float z = (v[j] - mean) * rs * __ldg(&ln_g[d]) + __ldg(&ln_b[d]);
                float sg = 1.f / (1.f + expf(-z));
                float slr = 0.6f * z + 0.4f * z * (2.f * sg - 1.f);
                p += slr * __ldg(&alpha_dot[head * 32 + d]);
            }
            p += __shfl_xor_sync(~0u, p, 1);
            p += __shfl_xor_sync(~0u, p, 2);
            if (q == 0)
                out[(size_t)erow * 8 + head] = p;
        }
    }
}

// ============ launch ============
extern "C" void kernel_launch(void* const* d_in, const int* in_sizes, int n_in,
                              void* d_out, int out_size) {
    const float* x_edge   = (const float*)d_in[0];
    const float* node_in  = (const float*)d_in[1];
    const float* edge_vec = (const float*)d_in[2];
    const int*   sp       = (const int*)d_in[3];
    const float* dot_w    = (const float*)d_in[4];
    const float* dot_b    = (const float*)d_in[5];
    const float* w0  = (const float*)d_in[6];
    const float* b0  = (const float*)d_in[7];
    const float* w1  = (const float*)d_in[8];
    const float* b1  = (const float*)d_in[9];
    const float* w2  = (const float*)d_in[10];
    const float* b2  = (const float*)d_in[11];
    const float* g0  = (const float*)d_in[12];
    const float* bb0 = (const float*)d_in[13];
    const float* g1  = (const float*)d_in[14];
    const float* bb1 = (const float*)d_in[15];
    const float* fcw = (const float*)d_in[16];
    const float* fcb = (const float*)d_in[17];
    const float* lng = (const float*)d_in[18];
    const float* lnb = (const float*)d_in[19];
    const float* ad  = (const float*)d_in[20];
    float* out = (float*)d_out;

    k01<<<NN, 256>>>(node_in, dot_w, dot_b, w2, fcw);

    cudaFuncSetAttribute(k2, cudaFuncAttributeMaxDynamicSharedMemorySize, SMEM_B);
    k2<<<NN, NTH, SMEM_B>>>(x_edge, edge_vec, sp,
                            w0, b0, w1, b1, b2, g0, bb0, g1, bb1,
                            fcb, lng, lnb, ad, out);
}